// round 11
// baseline (speedup 1.0000x reference)
#include <cuda_runtime.h>
#include <cstdint>

#define B_TOTAL 2048

__constant__ int c_FOFF[9] = {0,100000,150000,150010,150013,150113,150163,151163,151187};
__constant__ int c_EDIM[9] = {16,16,8,4,8,8,8,4,4};
__constant__ int c_EOFF[9] = {0,16,32,40,44,52,60,68,72};
__constant__ unsigned char c_F[77] = {
    0,0,0,0,0,0,0,0,0,0,0,0,0,0,0,0,
    1,1,1,1,1,1,1,1,1,1,1,1,1,1,1,1,
    2,2,2,2,2,2,2,2,
    3,3,3,3,
    4,4,4,4,4,4,4,4,
    5,5,5,5,5,5,5,5,
    6,6,6,6,6,6,6,6,
    7,7,7,7,
    8,8,8,8,
    0 /* c=76 is price, unused */};
#define NF_LAST 151192

struct P30 { const void* p[30]; };
typedef unsigned long long u64;

// H1 transposed, duplicated (v,v): [256 cols][2048 rows] u64 = 4 MB
__device__ u64 g_H1Td[256 * 2048];

__device__ __forceinline__ void ffma2(u64 &d, u64 a, u64 b) {
    asm("fma.rn.f32x2 %0, %1, %2, %0;" : "+l"(d) : "l"(a), "l"(b));
}
__device__ __forceinline__ u64 pack2(float x) {
    u64 r; asm("mov.b64 %0, {%1, %1};" : "=l"(r) : "f"(x)); return r;
}
__device__ __forceinline__ float2 unpack2(u64 v) {
    float2 f; asm("mov.b64 {%0, %1}, %2;" : "=f"(f.x), "=f"(f.y) : "l"(v)); return f;
}
__device__ __forceinline__ u64 d2u(double d) { return __double_as_longlong(d); }
__device__ __forceinline__ double u2d(u64 v) { return __longlong_as_double(v); }
__device__ __forceinline__ int read_id(const void* p, int i, bool is64) {
    return is64 ? (int)((const long long*)p)[i] : ((const int*)p)[i];
}
__device__ __forceinline__ unsigned smem_u32(const void* p) {
    return (unsigned)__cvta_generic_to_shared(p);
}
__device__ __forceinline__ void cp16(void* dst, const void* src) {
    asm volatile("cp.async.cg.shared.global [%0], [%1], 16;\n"
                 :: "r"(smem_u32(dst)), "l"(src) : "memory");
}
__device__ __forceinline__ void cp_commit() {
    asm volatile("cp.async.commit_group;\n" ::: "memory");
}
template<int N> __device__ __forceinline__ void cp_wait() {
    asm volatile("cp.async.wait_group %0;\n" :: "n"(N) : "memory");
}

// ============================ K1: X gather + L1 GEMM ============================
// grid 128: mt = bid>>2 (64 rows), nt = bid&3 (64 cols of 256). NT=256.
// smem: u64 sXTd[77*64] (39424B) | float sW[77*64] (19712B) | int sIdx[576] | float sPrice[64]
#define K1_OFF_XT    0
#define K1_OFF_W     39424
#define K1_OFF_IDX   59136
#define K1_OFF_PRICE 61440
#define K1_SMEM      61696

extern "C" __global__ void __launch_bounds__(256, 1)
k1_gemm(P30 a)
{
    extern __shared__ __align__(16) char smem[];
    u64*   sXTd   = (u64*)(smem + K1_OFF_XT);
    float* sW     = (float*)(smem + K1_OFF_W);
    int*   sIdx   = (int*)(smem + K1_OFF_IDX);
    float* sPrice = (float*)(smem + K1_OFF_PRICE);

    const int t  = threadIdx.x;
    const int w  = t >> 5;
    const int ln = t & 31;
    const int mt = blockIdx.x >> 2;
    const int nt = blockIdx.x & 3;
    const int m0 = mt * 64;

    // input-layout detection
    const u64* u0 = (const u64*)a.p[0];
    const bool is64 = ((u0[0] | u0[1] | u0[2] | u0[3]) < (1ULL << 20));
    const u64* u7 = (const u64*)a.p[7];
    const bool dict = (u7[0] < (1ULL << 40));

    const void* idp[9];
    #pragma unroll
    for (int f = 0; f < 7; f++) idp[f] = a.p[f];
    const float* price;
    if (dict) { idp[7] = a.p[7]; idp[8] = a.p[8]; price = (const float*)a.p[9]; }
    else      { price = (const float*)a.p[7]; idp[7] = a.p[8]; idp[8] = a.p[9]; }
    const float* emb[9];
    #pragma unroll
    for (int f = 0; f < 9; f++) emb[f] = (const float*)a.p[10 + f];
    const float* __restrict__ W1 = (const float*)a.p[22];
    const float* __restrict__ b1 = (const float*)a.p[23];

    // stage W1 tile [77][64] via cp.async
    for (int i = t; i < 77 * 16; i += 256) {
        int k = i >> 4, c4 = i & 15;
        cp16(sW + k * 64 + c4 * 4, W1 + k * 256 + nt * 64 + c4 * 4);
    }
    cp_commit();

    // ids + price for 64 samples
    for (int i = t; i < 64 * 9; i += 256) {
        int s = i / 9, f = i - s * 9;
        sIdx[i] = read_id(idp[f], m0 + s, is64);
    }
    if (t < 64) sPrice[t] = price[m0 + t];
    __syncthreads();

    // gather duplicated XT[77][64]
    for (int i = t; i < 77 * 64; i += 256) {
        int c = i >> 6, s = i & 63;
        float v;
        if (c == 76) v = sPrice[s];
        else {
            int f = c_F[c];
            v = emb[f][sIdx[s * 9 + f] * c_EDIM[f] + (c - c_EOFF[f])];
        }
        sXTd[c * 64 + s] = pack2(v);
    }
    cp_wait<0>();
    __syncthreads();

    // GEMM: per warp 32j x 16s; thread 4j x 4s
    {
        int jq = ln & 7, sg = ln >> 3;
        int j0 = (w & 1) * 32 + jq * 4;         // tile-local col 0..60
        int s0 = (w >> 1) * 16 + sg * 4;        // tile-local row 0..60
        u64 bbA = *(const u64*)(b1 + nt * 64 + j0);
        u64 bbB = *(const u64*)(b1 + nt * 64 + j0 + 2);
        u64 aA0 = bbA, aA1 = bbA, aA2 = bbA, aA3 = bbA;
        u64 aB0 = bbB, aB1 = bbB, aB2 = bbB, aB3 = bbB;
        const float* Wp = sW + j0;
        const u64*   Xp = sXTd + s0;
        #pragma unroll 7
        for (int k = 0; k < 77; k++) {
            double2 wd = *(const double2*)(Wp + k * 64);    // (wj0,wj1),(wj2,wj3)
            double2 xa = *(const double2*)(Xp + k * 64);    // dup s0, s0+1
            double2 xb = *(const double2*)(Xp + k * 64 + 2);
            u64 wA = d2u(wd.x), wB = d2u(wd.y);
            u64 x0 = d2u(xa.x), x1 = d2u(xa.y), x2 = d2u(xb.x), x3 = d2u(xb.y);
            ffma2(aA0, wA, x0); ffma2(aA1, wA, x1); ffma2(aA2, wA, x2); ffma2(aA3, wA, x3);
            ffma2(aB0, wB, x0); ffma2(aB1, wB, x1); ffma2(aB2, wB, x2); ffma2(aB3, wB, x3);
        }
        float2 A0 = unpack2(aA0), A1 = unpack2(aA1), A2 = unpack2(aA2), A3 = unpack2(aA3);
        float2 B0 = unpack2(aB0), B1 = unpack2(aB1), B2 = unpack2(aB2), B3 = unpack2(aB3);
        int colg = nt * 64 + j0;
        u64* p0 = g_H1Td + (colg    ) * 2048 + m0 + s0;
        u64* p1 = g_H1Td + (colg + 1) * 2048 + m0 + s0;
        u64* p2 = g_H1Td + (colg + 2) * 2048 + m0 + s0;
        u64* p3 = g_H1Td + (colg + 3) * 2048 + m0 + s0;
        ((double2*)p0)[0] = make_double2(u2d(pack2(fmaxf(A0.x,0.f))), u2d(pack2(fmaxf(A1.x,0.f))));
        ((double2*)p0)[1] = make_double2(u2d(pack2(fmaxf(A2.x,0.f))), u2d(pack2(fmaxf(A3.x,0.f))));
        ((double2*)p1)[0] = make_double2(u2d(pack2(fmaxf(A0.y,0.f))), u2d(pack2(fmaxf(A1.y,0.f))));
        ((double2*)p1)[1] = make_double2(u2d(pack2(fmaxf(A2.y,0.f))), u2d(pack2(fmaxf(A3.y,0.f))));
        ((double2*)p2)[0] = make_double2(u2d(pack2(fmaxf(B0.x,0.f))), u2d(pack2(fmaxf(B1.x,0.f))));
        ((double2*)p2)[1] = make_double2(u2d(pack2(fmaxf(B2.x,0.f))), u2d(pack2(fmaxf(B3.x,0.f))));
        ((double2*)p3)[0] = make_double2(u2d(pack2(fmaxf(B0.y,0.f))), u2d(pack2(fmaxf(B1.y,0.f))));
        ((double2*)p3)[1] = make_double2(u2d(pack2(fmaxf(B2.y,0.f))), u2d(pack2(fmaxf(B3.y,0.f))));
    }
}

// ================== K2: FM + dense + L2 + L3 + output (16 rows/block) ==================
// smem bytes:
#define K2_OFF_W2   0          // float[256*128]  131072
#define K2_OFF_W3   131072     // float[128*64]    32768
#define K2_OFF_H1   163840     // u64[256*18]      36864
#define K2_OFF_H2   200704     // u64[128*18]      18432
#define K2_OFF_H3   219136     // float[64*17]      4352
#define K2_OFF_BASE 223488
#define K2_OFF_PRICE 223552
#define K2_OFF_IDX  223616     // int[144]
#define K2_SMEM     224192

extern "C" __global__ void __launch_bounds__(256, 1)
k2_tail(P30 a, float* __restrict__ out, int B)
{
    extern __shared__ __align__(16) char smem[];
    float* sW2    = (float*)(smem + K2_OFF_W2);
    float* sW3    = (float*)(smem + K2_OFF_W3);
    u64*   sH1Td  = (u64*)(smem + K2_OFF_H1);
    u64*   sH2Td  = (u64*)(smem + K2_OFF_H2);
    float* sH3T   = (float*)(smem + K2_OFF_H3);
    float* sBase  = (float*)(smem + K2_OFF_BASE);
    float* sPrice = (float*)(smem + K2_OFF_PRICE);
    int*   sIdx   = (int*)(smem + K2_OFF_IDX);

    const int t  = threadIdx.x;
    const int w  = t >> 5;
    const int ln = t & 31;
    const int m0 = blockIdx.x * 16;

    // input-layout detection
    const u64* u0 = (const u64*)a.p[0];
    const bool is64 = ((u0[0] | u0[1] | u0[2] | u0[3]) < (1ULL << 20));
    const u64* u7 = (const u64*)a.p[7];
    const bool dict = (u7[0] < (1ULL << 40));

    const void* idp[9];
    #pragma unroll
    for (int f = 0; f < 7; f++) idp[f] = a.p[f];
    const float* price;
    if (dict) { idp[7] = a.p[7]; idp[8] = a.p[8]; price = (const float*)a.p[9]; }
    else      { price = (const float*)a.p[7]; idp[7] = a.p[8]; idp[8] = a.p[9]; }

    const float* __restrict__ w_dense = (const float*)a.p[19];
    const float* __restrict__ b_dense = (const float*)a.p[20];
    const float* __restrict__ fm_v    = (const float*)a.p[21];
    const float* __restrict__ W2 = (const float*)a.p[24];
    const float* __restrict__ b2 = (const float*)a.p[25];
    const float* __restrict__ W3 = (const float*)a.p[26];
    const float* __restrict__ b3 = (const float*)a.p[27];
    const float* __restrict__ Wo = (const float*)a.p[28];
    const float* __restrict__ bo = (const float*)a.p[29];

    // ---- one big cp.async burst: W2 (128K) + W3 (32K) + H1T tile (32K) ----
    {
        const float4* gW2 = (const float4*)W2;
        float4* dW2 = (float4*)sW2;
        #pragma unroll
        for (int i = 0; i < 32; i++) cp16(dW2 + t + i * 256, gW2 + t + i * 256);
        const float4* gW3 = (const float4*)W3;
        float4* dW3 = (float4*)sW3;
        #pragma unroll
        for (int i = 0; i < 8; i++) cp16(dW3 + t + i * 256, gW3 + t + i * 256);
        #pragma unroll
        for (int i = 0; i < 8; i++) {
            int idx = t + i * 256;              // 0..2047 : col = idx>>3, chunk c = idx&7
            int col = idx >> 3, c = idx & 7;
            cp16(sH1Td + col * 18 + c * 2, g_H1Td + col * 2048 + m0 + c * 2);
        }
        cp_commit();
    }

    // ---- ids + price (16 samples) ----
    if (t < 16 * 9) {
        int s = t / 9, f = t - s * 9;
        sIdx[t] = read_id(idp[f], m0 + s, is64);
    }
    if (t >= 160 && t < 176) sPrice[t - 160] = price[m0 + (t - 160)];
    __syncthreads();

    // ---- FM + dense: all 8 warps, half-warp per sample (overlaps staging) ----
    {
        int s = w * 2 + (ln >> 4);
        int e = ln & 15;
        float pv = sPrice[s] * 1e-3f;
        float fs = 0.f, ss = 0.f;
        #pragma unroll
        for (int f = 0; f < 9; f++) {
            int row = c_FOFF[f] + sIdx[s * 9 + f];
            float v = fm_v[row * 16 + e];
            fs += v; ss += v * v;
        }
        {
            float v = fm_v[NF_LAST * 16 + e];
            fs += pv * v; ss += pv * pv * v * v;
        }
        float val = fs * fs - ss;
        #pragma unroll
        for (int o = 8; o; o >>= 1) val += __shfl_xor_sync(0xffffffffu, val, o, 16);
        float fm = 0.5f * val;

        float dn = 0.f;
        if (e < 9)  dn = w_dense[c_FOFF[e] + sIdx[s * 9 + e]];
        if (e == 9) dn = pv * w_dense[NF_LAST];
        #pragma unroll
        for (int o = 8; o; o >>= 1) dn += __shfl_xor_sync(0xffffffffu, dn, o, 16);

        if (e == 0) sBase[s] = fm + dn + b_dense[0];
    }
    cp_wait<0>();
    __syncthreads();

    // ---- L2: K=256, N=128, 16 samples. thread: 4j x 2s. pure smem. ----
    {
        int jq = ln & 3, sg = ln >> 2;
        int j0 = w * 16 + jq * 4;
        int s0 = sg * 2;
        u64 bbA = *(const u64*)(b2 + j0);
        u64 bbB = *(const u64*)(b2 + j0 + 2);
        u64 a00 = bbA, a01 = bbA, a10 = bbB, a11 = bbB;
        const float* Wp = sW2 + j0;
        const u64*   Xp = sH1Td + s0;
        #pragma unroll 8
        for (int k = 0; k < 256; k++) {
            double2 wd = *(const double2*)(Wp + k * 128);
            double2 xd = *(const double2*)(Xp + k * 18);
            u64 wA = d2u(wd.x), wB = d2u(wd.y);
            u64 x0 = d2u(xd.x), x1 = d2u(xd.y);
            ffma2(a00, wA, x0); ffma2(a01, wA, x1);
            ffma2(a10, wB, x0); ffma2(a11, wB, x1);
        }
        float2 f00 = unpack2(a00), f01 = unpack2(a01);
        float2 f10 = unpack2(a10), f11 = unpack2(a11);
        u64* r0 = sH2Td + (j0    ) * 18 + s0;
        u64* r1 = sH2Td + (j0 + 1) * 18 + s0;
        u64* r2 = sH2Td + (j0 + 2) * 18 + s0;
        u64* r3 = sH2Td + (j0 + 3) * 18 + s0;
        ((double2*)r0)[0] = make_double2(u2d(pack2(fmaxf(f00.x,0.f))), u2d(pack2(fmaxf(f01.x,0.f))));
        ((double2*)r1)[0] = make_double2(u2d(pack2(fmaxf(f00.y,0.f))), u2d(pack2(fmaxf(f01.y,0.f))));
        ((double2*)r2)[0] = make_double2(u2d(pack2(fmaxf(f10.x,0.f))), u2d(pack2(fmaxf(f11.x,0.f))));
        ((double2*)r3)[0] = make_double2(u2d(pack2(fmaxf(f10.y,0.f))), u2d(pack2(fmaxf(f11.y,0.f))));
    }
    __syncthreads();

    // ---- L3: K=128, N=64. thread: 2j x 2s. pure smem. ----
    {
        int jq = ln & 3, sg = ln >> 2;
        int j0 = w * 8 + jq * 2;
        int s0 = sg * 2;
        u64 bb = *(const u64*)(b3 + j0);
        u64 a0 = bb, a1 = bb;
        const float* Wp = sW3 + j0;
        const u64*   Xp = sH2Td + s0;
        #pragma unroll 8
        for (int k = 0; k < 128; k++) {
            u64 wv = *(const u64*)(Wp + k * 64);
            double2 xd = *(const double2*)(Xp + k * 18);
            ffma2(a0, wv, d2u(xd.x));
            ffma2(a1, wv, d2u(xd.y));
        }
        float2 f0 = unpack2(a0), f1 = unpack2(a1);
        sH3T[(j0    ) * 17 + s0]     = fmaxf(f0.x, 0.f);
        sH3T[(j0    ) * 17 + s0 + 1] = fmaxf(f1.x, 0.f);
        sH3T[(j0 + 1) * 17 + s0]     = fmaxf(f0.y, 0.f);
        sH3T[(j0 + 1) * 17 + s0 + 1] = fmaxf(f1.y, 0.f);
    }
    __syncthreads();

    // ---- output: warps 0-3, 8 lanes per sample ----
    if (w < 4) {
        int s  = w * 4 + (ln >> 3);
        int q8 = ln & 7;
        float v = 0.f;
        #pragma unroll
        for (int q = 0; q < 8; q++)
            v += sH3T[(q8 * 8 + q) * 17 + s] * Wo[q8 * 8 + q];
        v += __shfl_xor_sync(0xffffffffu, v, 4, 8);
        v += __shfl_xor_sync(0xffffffffu, v, 2, 8);
        v += __shfl_xor_sync(0xffffffffu, v, 1, 8);
        if (q8 == 0 && m0 + s < B)
            out[m0 + s] = v + bo[0] + sBase[s];
    }
}

extern "C" void kernel_launch(void* const* d_in, const int* in_sizes, int n_in,
                              void* d_out, int out_size)
{
    (void)in_sizes; (void)n_in;
    P30 a;
    for (int i = 0; i < 30; i++) a.p[i] = d_in[i];
    cudaFuncSetAttribute(k1_gemm, cudaFuncAttributeMaxDynamicSharedMemorySize, K1_SMEM);
    cudaFuncSetAttribute(k2_tail, cudaFuncAttributeMaxDynamicSharedMemorySize, K2_SMEM);
    k1_gemm<<<128, 256, K1_SMEM>>>(a);
    k2_tail<<<128, 256, K2_SMEM>>>(a, (float*)d_out, out_size);
}

// round 12
// speedup vs baseline: 1.0830x; 1.0830x over previous
#include <cuda_runtime.h>
#include <cstdint>

#define TS   16
#define NT   512
#define NBLK 128

__constant__ int c_FOFF[9] = {0,100000,150000,150010,150013,150113,150163,151163,151187};
__constant__ int c_EDIM[9] = {16,16,8,4,8,8,8,4,4};
__constant__ int c_EOFF[9] = {0,16,32,40,44,52,60,68,72};
__constant__ unsigned char c_F[76] = {
    0,0,0,0,0,0,0,0,0,0,0,0,0,0,0,0,
    1,1,1,1,1,1,1,1,1,1,1,1,1,1,1,1,
    2,2,2,2,2,2,2,2,
    3,3,3,3,
    4,4,4,4,4,4,4,4,
    5,5,5,5,5,5,5,5,
    6,6,6,6,6,6,6,6,
    7,7,7,7,
    8,8,8,8};
#define NF_LAST 151192

struct P30 { const void* p[30]; };
typedef unsigned long long u64;

__device__ __forceinline__ void ffma2(u64 &d, u64 a, u64 b) {
    asm("fma.rn.f32x2 %0, %1, %2, %0;" : "+l"(d) : "l"(a), "l"(b));
}
__device__ __forceinline__ u64 pack2(float x) {
    u64 r; asm("mov.b64 %0, {%1, %1};" : "=l"(r) : "f"(x)); return r;
}
__device__ __forceinline__ float2 unpack2(u64 v) {
    float2 f; asm("mov.b64 {%0, %1}, %2;" : "=f"(f.x), "=f"(f.y) : "l"(v)); return f;
}
__device__ __forceinline__ u64 d2u(double d) { return __double_as_longlong(d); }
__device__ __forceinline__ double u2d(u64 v) { return __longlong_as_double(v); }
__device__ __forceinline__ int read_id(const void* p, int i, bool is64) {
    return is64 ? (int)((const long long*)p)[i] : ((const int*)p)[i];
}

// Activation rows: 16 dup-u64 + 4 pad = 20 u64 = 160B (40 words ≡ 8 mod 32 -> bank stagger)
#define RS 20

// dynamic smem byte offsets
#define OFF_XT    0            // u64[77][20]   12320
#define OFF_H1    12320        // u64[256][20]  40960
#define OFF_H2    53280        // u64[128][20]  20480
#define OFF_H3    73760        // float[64][17]  4352
#define OFF_BASE  78112
#define OFF_PRICE 78176
#define OFF_IDX   78240        // int[144]
#define SMEM_BYTES 78816

extern "C" __global__ void __launch_bounds__(NT, 1)
deepfm_kernel(P30 a, float* __restrict__ out, int B)
{
    extern __shared__ __align__(16) char smem[];
    u64*   sXTd   = (u64*)(smem + OFF_XT);
    u64*   sH1d   = (u64*)(smem + OFF_H1);
    u64*   sH2d   = (u64*)(smem + OFF_H2);
    float* sH3    = (float*)(smem + OFF_H3);
    float* sBase  = (float*)(smem + OFF_BASE);
    float* sPrice = (float*)(smem + OFF_PRICE);
    int*   sIdx   = (int*)(smem + OFF_IDX);

    const int t  = threadIdx.x;
    const int w  = t >> 5;
    const int ln = t & 31;
    const int s0blk = blockIdx.x * TS;

    // ---- input-layout detection (deterministic, data-driven) ----
    const u64* u0 = (const u64*)a.p[0];
    const bool is64 = ((u0[0] | u0[1] | u0[2] | u0[3]) < (1ULL << 20));
    const u64* u7 = (const u64*)a.p[7];
    const bool dict = (u7[0] < (1ULL << 40));

    const void* idp[9];
    #pragma unroll
    for (int f = 0; f < 7; f++) idp[f] = a.p[f];
    const float* price;
    if (dict) { idp[7] = a.p[7]; idp[8] = a.p[8]; price = (const float*)a.p[9]; }
    else      { price = (const float*)a.p[7]; idp[7] = a.p[8]; idp[8] = a.p[9]; }

    const float* emb[9];
    #pragma unroll
    for (int f = 0; f < 9; f++) emb[f] = (const float*)a.p[10 + f];
    const float* __restrict__ w_dense = (const float*)a.p[19];
    const float* __restrict__ b_dense = (const float*)a.p[20];
    const float* __restrict__ fm_v    = (const float*)a.p[21];
    const float* __restrict__ W1 = (const float*)a.p[22];
    const float* __restrict__ b1 = (const float*)a.p[23];
    const float* __restrict__ W2 = (const float*)a.p[24];
    const float* __restrict__ b2 = (const float*)a.p[25];
    const float* __restrict__ W3 = (const float*)a.p[26];
    const float* __restrict__ b3 = (const float*)a.p[27];
    const float* __restrict__ Wo = (const float*)a.p[28];
    const float* __restrict__ bo = (const float*)a.p[29];

    // ---- gather ids + price ----
    if (t < TS * 9) {
        int s = t / 9, f = t - s * 9;
        sIdx[s * 9 + f] = read_id(idp[f], s0blk + s, is64);
    }
    if (t >= 160 && t < 160 + TS) sPrice[t - 160] = price[s0blk + (t - 160)];
    __syncthreads();

    // ---- warps 0-7: FM + dense; warps 8-15: build duplicated XT[77][16] ----
    if (w < 8) {
        int s = w * 2 + (ln >> 4);
        int e = ln & 15;
        float pv = sPrice[s] * 1e-3f;
        float fs = 0.f, ss = 0.f;
        #pragma unroll
        for (int f = 0; f < 9; f++) {
            int row = c_FOFF[f] + sIdx[s * 9 + f];
            float v = fm_v[row * 16 + e];
            fs += v; ss += v * v;
        }
        {
            float v = fm_v[NF_LAST * 16 + e];
            fs += pv * v; ss += pv * pv * v * v;
        }
        float val = fs * fs - ss;
        #pragma unroll
        for (int o = 8; o; o >>= 1) val += __shfl_xor_sync(0xffffffffu, val, o, 16);
        float fm = 0.5f * val;

        float dn = 0.f;
        if (e < 9)  dn = w_dense[c_FOFF[e] + sIdx[s * 9 + e]];
        if (e == 9) dn = pv * w_dense[NF_LAST];
        #pragma unroll
        for (int o = 8; o; o >>= 1) dn += __shfl_xor_sync(0xffffffffu, dn, o, 16);

        if (e == 0) sBase[s] = fm + dn + b_dense[0];
    } else {
        for (int idx = t - 256; idx < TS * 77; idx += 256) {
            int s = idx & 15, c = idx >> 4;
            float v;
            if (c == 76) v = sPrice[s];
            else {
                int f = c_F[c];
                v = emb[f][sIdx[s * 9 + f] * c_EDIM[f] + (c - c_EOFF[f])];
            }
            sXTd[c * RS + s] = pack2(v);
        }
    }
    __syncthreads();

    // ---- Layer 1: K=77, N=256, 16 warps. Thread: 1 j-pair x 4 samples. ----
    {
        int jgl = ln & 7, sg = ln >> 3;
        int j0 = (w * 8 + jgl) * 2;        // 0..254
        int s0 = sg * 4;
        u64 bb = *(const u64*)(b1 + j0);
        u64 a0 = bb, a1 = bb, a2 = bb, a3 = bb;   // acc_s = (v_j0, v_j1)
        const float* Wp = W1 + j0;
        const u64*   Xp = sXTd + s0;
        #pragma unroll 11
        for (int k = 0; k < 77; k++) {
            u64 wv = *(const u64*)(Wp + k * 256);
            double2 xa = *(const double2*)(Xp + k * RS);
            double2 xb = *(const double2*)(Xp + k * RS + 2);
            ffma2(a0, wv, d2u(xa.x)); ffma2(a1, wv, d2u(xa.y));
            ffma2(a2, wv, d2u(xb.x)); ffma2(a3, wv, d2u(xb.y));
        }
        float2 f0 = unpack2(a0), f1 = unpack2(a1), f2 = unpack2(a2), f3 = unpack2(a3);
        u64* r0 = sH1d + j0 * RS + s0;
        ((double2*)r0)[0] = make_double2(u2d(pack2(fmaxf(f0.x,0.f))), u2d(pack2(fmaxf(f1.x,0.f))));
        ((double2*)r0)[1] = make_double2(u2d(pack2(fmaxf(f2.x,0.f))), u2d(pack2(fmaxf(f3.x,0.f))));
        u64* r1 = sH1d + (j0 + 1) * RS + s0;
        ((double2*)r1)[0] = make_double2(u2d(pack2(fmaxf(f0.y,0.f))), u2d(pack2(fmaxf(f1.y,0.f))));
        ((double2*)r1)[1] = make_double2(u2d(pack2(fmaxf(f2.y,0.f))), u2d(pack2(fmaxf(f3.y,0.f))));
    }
    __syncthreads();

    // ---- Layer 2: K=256, N=128, 16 warps. Thread: 1 j-pair x 2 samples. ----
    {
        int jql = ln & 3, sg = ln >> 2;    // sg 0..7
        int j0 = w * 8 + jql * 2;          // 0..126
        int s0 = sg * 2;
        u64 bb = *(const u64*)(b2 + j0);
        u64 a0 = bb, a1 = bb;
        const float* Wp = W2 + j0;
        const u64*   Xp = sH1d + s0;
        #pragma unroll 8
        for (int k = 0; k < 256; k++) {
            u64 wv = *(const u64*)(Wp + k * 128);
            double2 xd = *(const double2*)(Xp + k * RS);
            ffma2(a0, wv, d2u(xd.x));
            ffma2(a1, wv, d2u(xd.y));
        }
        float2 f0 = unpack2(a0), f1 = unpack2(a1);
        u64* r0 = sH2d + j0 * RS + s0;
        ((double2*)r0)[0] = make_double2(u2d(pack2(fmaxf(f0.x,0.f))), u2d(pack2(fmaxf(f1.x,0.f))));
        u64* r1 = sH2d + (j0 + 1) * RS + s0;
        ((double2*)r1)[0] = make_double2(u2d(pack2(fmaxf(f0.y,0.f))), u2d(pack2(fmaxf(f1.y,0.f))));
    }
    __syncthreads();

    // ---- Layer 3: K=128, N=64, 16 warps. Thread: 1 j-pair x 1 sample. ----
    {
        int jp = ln & 1, s = ln >> 1;      // s 0..15
        int j0 = w * 4 + jp * 2;           // 0..62
        u64 acc = *(const u64*)(b3 + j0);
        const float* Wp = W3 + j0;
        const u64*   Xp = sH2d + s;
        #pragma unroll 8
        for (int k = 0; k < 128; k++) {
            u64 wv = *(const u64*)(Wp + k * 64);
            ffma2(acc, wv, Xp[k * RS]);
        }
        float2 f = unpack2(acc);
        sH3[(j0    ) * 17 + s] = fmaxf(f.x, 0.f);
        sH3[(j0 + 1) * 17 + s] = fmaxf(f.y, 0.f);
    }
    __syncthreads();

    // ---- Output: warps 0-3, 8 lanes per sample ----
    if (w < 4) {
        int s  = w * 4 + (ln >> 3);
        int q8 = ln & 7;
        float v = 0.f;
        #pragma unroll
        for (int q = 0; q < 8; q++)
            v += sH3[(q8 * 8 + q) * 17 + s] * Wo[q8 * 8 + q];
        v += __shfl_xor_sync(0xffffffffu, v, 4, 8);
        v += __shfl_xor_sync(0xffffffffu, v, 2, 8);
        v += __shfl_xor_sync(0xffffffffu, v, 1, 8);
        if (q8 == 0 && s0blk + s < B)
            out[s0blk + s] = v + bo[0] + sBase[s];
    }
}

extern "C" void kernel_launch(void* const* d_in, const int* in_sizes, int n_in,
                              void* d_out, int out_size)
{
    (void)in_sizes; (void)n_in;
    P30 a;
    for (int i = 0; i < 30; i++) a.p[i] = d_in[i];
    cudaFuncSetAttribute(deepfm_kernel, cudaFuncAttributeMaxDynamicSharedMemorySize, SMEM_BYTES);
    deepfm_kernel<<<NBLK, NT, SMEM_BYTES>>>(a, (float*)d_out, out_size);
}